// round 5
// baseline (speedup 1.0000x reference)
#include <cuda_runtime.h>
#include <cstdint>

#define N_NODES 262144
#define DIM     256
#define HID     128
#define NGRAPH  2048
#define NTILES  2048          // N_NODES / 128
#define SGRID   152

// smem layout for score kernel
#define WSF_BYTES   131072    // uint32 wsf[32 ksteps][16 ntiles][32 lanes][2]
#define XS_BYTES    36864     // float xs[2][128][36]
#define B1F_BYTES   4096      // float b1f[16][32][2]
#define W2F_BYTES   4096
#define SMEM_BYTES  (WSF_BYTES + XS_BYTES + B1F_BYTES + W2F_BYTES)   // 176128

__device__ float g_scores[N_NODES];
__device__ float g_w[N_NODES];

// ---------------------------------------------------------------------------
__device__ __forceinline__ uint32_t f2tf32(float f) {
    uint32_t u;
    asm("cvt.rna.tf32.f32 %0, %1;" : "=r"(u) : "f"(f));
    return u;
}

__device__ __forceinline__ void mma_tf32(float* c,
                                         uint32_t a0, uint32_t a1, uint32_t a2, uint32_t a3,
                                         uint32_t b0, uint32_t b1) {
    asm volatile(
        "mma.sync.aligned.m16n8k8.row.col.f32.tf32.tf32.f32 "
        "{%0,%1,%2,%3}, {%4,%5,%6,%7}, {%8,%9}, {%0,%1,%2,%3};"
        : "+f"(c[0]), "+f"(c[1]), "+f"(c[2]), "+f"(c[3])
        : "r"(a0), "r"(a1), "r"(a2), "r"(a3), "r"(b0), "r"(b1));
}

__device__ __forceinline__ int lower_bound_i(const int* __restrict__ b, int n, int key) {
    int lo = 0, hi = n;
    while (lo < hi) {
        int mid = (lo + hi) >> 1;
        if (b[mid] < key) lo = mid + 1; else hi = mid;
    }
    return lo;
}

__device__ __forceinline__ float warp_max(float v) {
    #pragma unroll
    for (int o = 16; o; o >>= 1) v = fmaxf(v, __shfl_xor_sync(0xffffffffu, v, o));
    return v;
}
__device__ __forceinline__ float warp_sum(float v) {
    #pragma unroll
    for (int o = 16; o; o >>= 1) v += __shfl_xor_sync(0xffffffffu, v, o);
    return v;
}

// ---------------------------------------------------------------------------
// Kernel 1: scores[i] = b2 + sum_j W2[j] * relu(b1[j] + sum_k x[i][k]*W1[k][j])
// Persistent blocks; tile = 128 nodes; warp computes 16 nodes x 128 j via
// tf32 mma.sync m16n8k8; W1 pre-staged in smem in B-fragment order.
// ---------------------------------------------------------------------------
__global__ void __launch_bounds__(256, 1)
score_kernel(const float* __restrict__ x,
             const float* __restrict__ W1,
             const float* __restrict__ b1,
             const float* __restrict__ W2,
             const float* __restrict__ b2) {
    extern __shared__ unsigned char smem[];
    uint32_t* wsf = (uint32_t*)smem;                          // [ks][nt][lane][2]
    float*    xs  = (float*)(smem + WSF_BYTES);               // [2][128][36]
    float*    b1f = (float*)(smem + WSF_BYTES + XS_BYTES);    // [nt][lane][2]
    float*    w2f = b1f + 1024;

    const int tid  = threadIdx.x;
    const int lane = tid & 31;
    const int warp = tid >> 5;

    // --- stage W1 as tf32 B-fragments: b0 = W1[ks*8 + (lane&3)][nt*8 + lane/4]
    for (int i = tid; i < 32 * 16 * 32; i += 256) {
        int l = i & 31, nt = (i >> 5) & 15, ks = i >> 9;
        int col = nt * 8 + (l >> 2);
        int r0  = ks * 8 + (l & 3);
        wsf[2 * i + 0] = f2tf32(W1[r0 * HID + col]);
        wsf[2 * i + 1] = f2tf32(W1[(r0 + 4) * HID + col]);
    }
    // --- stage b1 / W2 in C-fragment column order: cols nt*8 + 2*(lane&3) {,+1}
    for (int i = tid; i < 16 * 32; i += 256) {
        int l = i & 31, nt = i >> 5;
        int c0 = nt * 8 + 2 * (l & 3);
        b1f[2 * i + 0] = b1[c0];
        b1f[2 * i + 1] = b1[c0 + 1];
        w2f[2 * i + 0] = W2[c0];
        w2f[2 * i + 1] = W2[c0 + 1];
    }
    const float b2v = b2[0];

    const int grid = gridDim.x;
    const int srow = tid >> 3;        // staging row 0..31 (thread covers +0,+32,+64,+96)
    const int scol = (tid & 7) * 4;   // staging col offset within 32-wide chunk

    // --- prologue: chunk 0 of first tile into buffer 0
    {
        int t0 = blockIdx.x;
        if (t0 < NTILES) {
            #pragma unroll
            for (int q = 0; q < 4; q++) {
                int row = srow + 32 * q;
                float4 v = *(const float4*)(x + (t0 * 128 + row) * DIM + scol);
                *(float4*)(xs + row * 36 + scol) = v;
            }
        }
    }
    __syncthreads();

    const int rA = warp * 16 + (lane >> 2);   // A-frag row within tile
    const int t4 = lane & 3;

    for (int tile = blockIdx.x; tile < NTILES; tile += grid) {
        float c[16][4];
        #pragma unroll
        for (int nt = 0; nt < 16; nt++)
            #pragma unroll
            for (int q = 0; q < 4; q++) c[nt][q] = 0.0f;

        #pragma unroll 1
        for (int kc = 0; kc < 8; kc++) {
            // prefetch next chunk (next tile's chunk 0 when kc==7)
            int ptile = (kc < 7) ? tile : (tile + grid);
            int pkc   = (kc + 1) & 7;
            bool pv   = (ptile < NTILES);
            float4 pr[4];
            if (pv) {
                #pragma unroll
                for (int q = 0; q < 4; q++) {
                    int row = srow + 32 * q;
                    pr[q] = *(const float4*)(x + (ptile * 128 + row) * DIM + pkc * 32 + scol);
                }
            }

            // compute 4 k-steps from current buffer
            const float* xb = xs + (kc & 1) * (128 * 36);
            #pragma unroll
            for (int ksl = 0; ksl < 4; ksl++) {
                int k0 = ksl * 8;
                uint32_t a0 = f2tf32(xb[rA * 36 + k0 + t4]);
                uint32_t a1 = f2tf32(xb[(rA + 8) * 36 + k0 + t4]);
                uint32_t a2 = f2tf32(xb[rA * 36 + k0 + t4 + 4]);
                uint32_t a3 = f2tf32(xb[(rA + 8) * 36 + k0 + t4 + 4]);
                int ks = kc * 4 + ksl;
                const uint32_t* wb = wsf + (ks * 512 + lane) * 2;
                #pragma unroll
                for (int nt = 0; nt < 16; nt++) {
                    uint32_t bb0 = wb[nt * 64];
                    uint32_t bb1 = wb[nt * 64 + 1];
                    mma_tf32(c[nt], a0, a1, a2, a3, bb0, bb1);
                }
            }

            // store prefetched chunk into other buffer
            if (pv) {
                float* xd = xs + ((kc + 1) & 1) * (128 * 36);
                #pragma unroll
                for (int q = 0; q < 4; q++) {
                    int row = srow + 32 * q;
                    *(float4*)(xd + row * 36 + scol) = pr[q];
                }
            }
            __syncthreads();
        }

        // --- epilogue: bias + relu + dot with W2, reduce over j
        float p0 = 0.0f, p8 = 0.0f;
        #pragma unroll
        for (int nt = 0; nt < 16; nt++) {
            int bi = (nt * 32 + lane) * 2;
            float q0 = b1f[bi], q1 = b1f[bi + 1];
            float w0 = w2f[bi], w1 = w2f[bi + 1];
            p0 += fmaxf(c[nt][0] + q0, 0.0f) * w0 + fmaxf(c[nt][1] + q1, 0.0f) * w1;
            p8 += fmaxf(c[nt][2] + q0, 0.0f) * w0 + fmaxf(c[nt][3] + q1, 0.0f) * w1;
        }
        p0 += __shfl_xor_sync(0xffffffffu, p0, 1);
        p0 += __shfl_xor_sync(0xffffffffu, p0, 2);
        p8 += __shfl_xor_sync(0xffffffffu, p8, 1);
        p8 += __shfl_xor_sync(0xffffffffu, p8, 2);
        if ((lane & 3) == 0) {
            int row = tile * 128 + warp * 16 + (lane >> 2);
            g_scores[row]     = p0 + b2v;
            g_scores[row + 8] = p8 + b2v;
        }
    }
}

// ---------------------------------------------------------------------------
// Kernel 2: per-graph segment softmax -> weights (batch is sorted)
// ---------------------------------------------------------------------------
__global__ void __launch_bounds__(256)
softmax_kernel(const int* __restrict__ batch) {
    const int g = blockIdx.x;
    const int tid = threadIdx.x;
    const int lane = tid & 31, wid = tid >> 5;
    __shared__ int sse[2];
    __shared__ float red[8];

    if (tid < 2) sse[tid] = lower_bound_i(batch, N_NODES, g + tid);
    __syncthreads();
    const int start = sse[0], end = sse[1];

    // max
    float m = -1e30f;
    for (int i = start + tid; i < end; i += 256) m = fmaxf(m, g_scores[i]);
    m = warp_max(m);
    if (lane == 0) red[wid] = m;
    __syncthreads();
    if (tid == 0) {
        float v = red[0];
        #pragma unroll
        for (int k = 1; k < 8; k++) v = fmaxf(v, red[k]);
        red[0] = v;
    }
    __syncthreads();
    const float M = red[0];
    __syncthreads();

    // exp + sum
    float s = 0.0f;
    for (int i = start + tid; i < end; i += 256) {
        float e = __expf(g_scores[i] - M);
        g_w[i] = e;
        s += e;
    }
    s = warp_sum(s);
    if (lane == 0) red[wid] = s;
    __syncthreads();
    if (tid == 0) {
        float v = red[0];
        #pragma unroll
        for (int k = 1; k < 8; k++) v += red[k];
        red[0] = v;
    }
    __syncthreads();
    const float inv = 1.0f / red[0];

    for (int i = start + tid; i < end; i += 256) g_w[i] *= inv;
}

// ---------------------------------------------------------------------------
// Kernel 3: out[g][d] = sum_{i in graph g} w[i] * x[i][d]
// One block per graph, thread d owns column d. Coalesced row reads, no atomics.
// ---------------------------------------------------------------------------
__global__ void __launch_bounds__(256)
pool_kernel(const int* __restrict__ batch,
            const float* __restrict__ x,
            float* __restrict__ out) {
    const int g = blockIdx.x;
    const int tid = threadIdx.x;
    __shared__ int sse[2];
    __shared__ float sw[256];

    if (tid < 2) sse[tid] = lower_bound_i(batch, N_NODES, g + tid);
    __syncthreads();
    const int start = sse[0], end = sse[1];

    float a0 = 0.0f, a1 = 0.0f, a2 = 0.0f, a3 = 0.0f;
    for (int base = start; base < end; base += 256) {
        int m = end - base;
        if (m > 256) m = 256;
        __syncthreads();
        if (tid < m) sw[tid] = g_w[base + tid];
        __syncthreads();
        int j = 0;
        for (; j + 3 < m; j += 4) {
            const float* xp = x + (size_t)(base + j) * DIM + tid;
            a0 = fmaf(sw[j],     xp[0],       a0);
            a1 = fmaf(sw[j + 1], xp[DIM],     a1);
            a2 = fmaf(sw[j + 2], xp[2 * DIM], a2);
            a3 = fmaf(sw[j + 3], xp[3 * DIM], a3);
        }
        for (; j < m; j++)
            a0 = fmaf(sw[j], x[(size_t)(base + j) * DIM + tid], a0);
    }
    out[g * DIM + tid] = (a0 + a1) + (a2 + a3);
}

// ---------------------------------------------------------------------------
extern "C" void kernel_launch(void* const* d_in, const int* in_sizes, int n_in,
                              void* d_out, int out_size) {
    const float* x     = (const float*)d_in[0];
    const int*   batch = (const int*)d_in[1];
    // d_in[2] = num_graphs (constant 2048, unused)
    const float* W1 = (const float*)d_in[3];
    const float* b1 = (const float*)d_in[4];
    const float* W2 = (const float*)d_in[5];
    const float* b2 = (const float*)d_in[6];
    float* out = (float*)d_out;

    cudaFuncSetAttribute(score_kernel, cudaFuncAttributeMaxDynamicSharedMemorySize, SMEM_BYTES);
    score_kernel<<<SGRID, 256, SMEM_BYTES>>>(x, W1, b1, W2, b2);
    softmax_kernel<<<NGRAPH, 256>>>(batch);
    pool_kernel<<<NGRAPH, 256>>>(batch, x, out);
}